// round 1
// baseline (speedup 1.0000x reference)
#include <cuda_runtime.h>
#include <cuda_fp16.h>
#include <mma.h>

using namespace nvcuda;

// Problem dims
constexpr int B_ = 4, E_ = 8, C_ = 2048, D_ = 1024, F_ = 2816;
constexpr int BM = 128, BN = 64, BK = 32;

// -------- scratch (allocation-free: __device__ globals) --------
__device__ __half g_xh [(size_t)B_ * E_ * C_ * D_];   // x in fp16        134 MB
__device__ __half g_w1h[(size_t)E_ * D_ * F_];        // w1 fp16           46 MB
__device__ __half g_w3h[(size_t)E_ * D_ * F_];        // w3 fp16           46 MB
__device__ __half g_w2h[(size_t)E_ * F_ * D_];        // w2 fp16           46 MB
__device__ __half g_hh [(size_t)B_ * E_ * C_ * F_];   // H = silu(g)*u    369 MB

// -------- cp.async helpers --------
__device__ __forceinline__ void cp16(void* smem_dst, const void* gsrc) {
    unsigned saddr = (unsigned)__cvta_generic_to_shared(smem_dst);
    asm volatile("cp.async.cg.shared.global [%0], [%1], 16;\n" ::"r"(saddr), "l"(gsrc));
}
__device__ __forceinline__ void cp_commit() {
    asm volatile("cp.async.commit_group;\n");
}
__device__ __forceinline__ void cp_wait1() {
    asm volatile("cp.async.wait_group 1;\n");
}
__device__ __forceinline__ void cp_wait0() {
    asm volatile("cp.async.wait_group 0;\n");
}

// -------- fp32 -> fp16 convert --------
__global__ void cvt_kernel(const float4* __restrict__ in, __half2* __restrict__ out, int n4) {
    int i = blockIdx.x * 256 + threadIdx.x;
    if (i >= n4) return;
    float4 v = in[i];
    out[2 * i + 0] = __floats2half2_rn(v.x, v.y);
    out[2 * i + 1] = __floats2half2_rn(v.z, v.w);
}

// ============================================================
// GEMM1: gate = X@W1, up = X@W3, H = silu(gate)*up   (per b,e)
// X: [C, D] fp16 (ld=D), W: [D, F] fp16 (ld=F), H: [C, F] fp16
// Tile: BM=128 x BN=64, BK=32, 256 threads, double-buffered cp.async
// ============================================================
struct SmemG1 {
    __half a [2][BM * 40];  // 128 x 32, ld 40 (pad 8)
    __half b1[2][BK * 72];  // 32 x 64, ld 72 (pad 8)
    __half b3[2][BK * 72];
};
union SmemU1 {
    SmemG1 t;
    float  epi[8][32 * 36];  // per-warp 32x32 fp32 patch, ld 36
};

__global__ __launch_bounds__(256) void gemm1_kernel() {
    __shared__ SmemU1 sm;

    const int tid = threadIdx.x;
    const int be  = blockIdx.z;         // b*8 + e
    const int e   = be & 7;
    const int m0  = blockIdx.y * BM;
    const int n0  = blockIdx.x * BN;

    const __half* A  = g_xh  + ((size_t)be * C_ + m0) * D_;
    const __half* B1 = g_w1h + (size_t)e * D_ * F_ + n0;
    const __half* B3 = g_w3h + (size_t)e * D_ * F_ + n0;
    __half*       Ho = g_hh  + ((size_t)be * C_ + m0) * F_ + n0;

    const int wid  = tid >> 5;
    const int lane = tid & 31;
    const int wm   = wid >> 1;   // 0..3  (M dir)
    const int wn   = wid & 1;    // 0..1  (N dir)

    wmma::fragment<wmma::accumulator, 16, 16, 16, float> aG[2][2], aU[2][2];
#pragma unroll
    for (int i = 0; i < 2; i++)
#pragma unroll
        for (int j = 0; j < 2; j++) {
            wmma::fill_fragment(aG[i][j], 0.0f);
            wmma::fill_fragment(aU[i][j], 0.0f);
        }

    // stage loader (inlined twice via macro-ish lambda)
    auto load_stage = [&](int s, int k0) {
#pragma unroll
        for (int j = 0; j < 2; j++) {
            int c   = tid + j * 256;           // 0..511
            int r   = c >> 2;                  // 0..127
            int col = (c & 3) * 8;             // 0,8,16,24
            cp16(&sm.t.a[s][r * 40 + col], A + (size_t)r * D_ + k0 + col);
        }
        {
            int r   = tid >> 3;                // 0..31
            int col = (tid & 7) * 8;           // 0..56
            cp16(&sm.t.b1[s][r * 72 + col], B1 + (size_t)(k0 + r) * F_ + col);
            cp16(&sm.t.b3[s][r * 72 + col], B3 + (size_t)(k0 + r) * F_ + col);
        }
    };

    load_stage(0, 0);
    cp_commit();

    const int NK = D_ / BK;  // 32
    for (int kt = 0; kt < NK; kt++) {
        const int s = kt & 1;
        if (kt + 1 < NK) {
            load_stage(s ^ 1, (kt + 1) * BK);
            cp_commit();
            cp_wait1();
        } else {
            cp_wait0();
        }
        __syncthreads();

        const __half* sa  = sm.t.a[s];
        const __half* sb1 = sm.t.b1[s];
        const __half* sb3 = sm.t.b3[s];
#pragma unroll
        for (int ks = 0; ks < 2; ks++) {
            const int k16 = ks * 16;
            wmma::fragment<wmma::matrix_a, 16, 16, 16, __half, wmma::row_major> af[2];
            wmma::load_matrix_sync(af[0], sa + (wm * 32 + 0)  * 40 + k16, 40);
            wmma::load_matrix_sync(af[1], sa + (wm * 32 + 16) * 40 + k16, 40);
            wmma::fragment<wmma::matrix_b, 16, 16, 16, __half, wmma::row_major> bf1[2], bf3[2];
#pragma unroll
            for (int j = 0; j < 2; j++) {
                wmma::load_matrix_sync(bf1[j], sb1 + k16 * 72 + wn * 32 + j * 16, 72);
                wmma::load_matrix_sync(bf3[j], sb3 + k16 * 72 + wn * 32 + j * 16, 72);
            }
#pragma unroll
            for (int i = 0; i < 2; i++)
#pragma unroll
                for (int j = 0; j < 2; j++) {
                    wmma::mma_sync(aG[i][j], af[i], bf1[j], aG[i][j]);
                    wmma::mma_sync(aU[i][j], af[i], bf3[j], aU[i][j]);
                }
        }
        __syncthreads();
    }

    // Epilogue: SwiGLU elementwise on fragments (identical layout for same frag type)
#pragma unroll
    for (int i = 0; i < 2; i++)
#pragma unroll
        for (int j = 0; j < 2; j++)
#pragma unroll
            for (int t = 0; t < aG[i][j].num_elements; t++) {
                float g = aG[i][j].x[t];
                float u = aU[i][j].x[t];
                aG[i][j].x[t] = u * (g / (1.0f + __expf(-g)));
            }

    // Stage via per-warp smem patch (union reuse; all warps past last sync),
    // then write fp16 H with 16B vector stores.
    float* ep = sm.epi[wid];
#pragma unroll
    for (int i = 0; i < 2; i++)
#pragma unroll
        for (int j = 0; j < 2; j++)
            wmma::store_matrix_sync(ep + i * 16 * 36 + j * 16, aG[i][j], 36, wmma::mem_row_major);
    __syncwarp();

    __half*      orow = Ho + (size_t)(wm * 32 + lane) * F_ + wn * 32;
    const float* er   = ep + lane * 36;
#pragma unroll
    for (int c4 = 0; c4 < 4; c4++) {
        __half2 h0 = __floats2half2_rn(er[c4 * 8 + 0], er[c4 * 8 + 1]);
        __half2 h1 = __floats2half2_rn(er[c4 * 8 + 2], er[c4 * 8 + 3]);
        __half2 h2 = __floats2half2_rn(er[c4 * 8 + 4], er[c4 * 8 + 5]);
        __half2 h3 = __floats2half2_rn(er[c4 * 8 + 6], er[c4 * 8 + 7]);
        uint4 v;
        v.x = *reinterpret_cast<unsigned*>(&h0);
        v.y = *reinterpret_cast<unsigned*>(&h1);
        v.z = *reinterpret_cast<unsigned*>(&h2);
        v.w = *reinterpret_cast<unsigned*>(&h3);
        *reinterpret_cast<uint4*>(orow + c4 * 8) = v;
    }
}

// ============================================================
// GEMM2: out = H @ W2    (per b,e)
// H: [C, F] fp16 (ld=F), W2: [F, D] fp16 (ld=D), out fp32 [C, D]
// ============================================================
struct SmemG2 {
    __half a[2][BM * 40];
    __half b[2][BK * 72];
};

__global__ __launch_bounds__(256) void gemm2_kernel(float* __restrict__ out) {
    __shared__ SmemG2 sm;

    const int tid = threadIdx.x;
    const int be  = blockIdx.z;
    const int e   = be & 7;
    const int m0  = blockIdx.y * BM;
    const int n0  = blockIdx.x * BN;

    const __half* A  = g_hh  + ((size_t)be * C_ + m0) * F_;
    const __half* Bw = g_w2h + (size_t)e * F_ * D_ + n0;
    float*        Co = out   + ((size_t)be * C_ + m0) * D_ + n0;

    const int wid = tid >> 5;
    const int wm  = wid >> 1;
    const int wn  = wid & 1;

    wmma::fragment<wmma::accumulator, 16, 16, 16, float> acc[2][2];
#pragma unroll
    for (int i = 0; i < 2; i++)
#pragma unroll
        for (int j = 0; j < 2; j++) wmma::fill_fragment(acc[i][j], 0.0f);

    auto load_stage = [&](int s, int k0) {
#pragma unroll
        for (int j = 0; j < 2; j++) {
            int c   = tid + j * 256;
            int r   = c >> 2;
            int col = (c & 3) * 8;
            cp16(&sm.a[s][r * 40 + col], A + (size_t)r * F_ + k0 + col);
        }
        {
            int r   = tid >> 3;
            int col = (tid & 7) * 8;
            cp16(&sm.b[s][r * 72 + col], Bw + (size_t)(k0 + r) * D_ + col);
        }
    };

    load_stage(0, 0);
    cp_commit();

    const int NK = F_ / BK;  // 88
    for (int kt = 0; kt < NK; kt++) {
        const int s = kt & 1;
        if (kt + 1 < NK) {
            load_stage(s ^ 1, (kt + 1) * BK);
            cp_commit();
            cp_wait1();
        } else {
            cp_wait0();
        }
        __syncthreads();

        const __half* sa = sm.a[s];
        const __half* sb = sm.b[s];
#pragma unroll
        for (int ks = 0; ks < 2; ks++) {
            const int k16 = ks * 16;
            wmma::fragment<wmma::matrix_a, 16, 16, 16, __half, wmma::row_major> af[2];
            wmma::load_matrix_sync(af[0], sa + (wm * 32 + 0)  * 40 + k16, 40);
            wmma::load_matrix_sync(af[1], sa + (wm * 32 + 16) * 40 + k16, 40);
            wmma::fragment<wmma::matrix_b, 16, 16, 16, __half, wmma::row_major> bf[2];
#pragma unroll
            for (int j = 0; j < 2; j++)
                wmma::load_matrix_sync(bf[j], sb + k16 * 72 + wn * 32 + j * 16, 72);
#pragma unroll
            for (int i = 0; i < 2; i++)
#pragma unroll
                for (int j = 0; j < 2; j++)
                    wmma::mma_sync(acc[i][j], af[i], bf[j], acc[i][j]);
        }
        __syncthreads();
    }

    // fp32 output straight to global
#pragma unroll
    for (int i = 0; i < 2; i++)
#pragma unroll
        for (int j = 0; j < 2; j++)
            wmma::store_matrix_sync(Co + (size_t)(wm * 32 + i * 16) * D_ + wn * 32 + j * 16,
                                    acc[i][j], D_, wmma::mem_row_major);
}

// ============================================================
// launch
// ============================================================
extern "C" void kernel_launch(void* const* d_in, const int* in_sizes, int n_in,
                              void* d_out, int out_size) {
    const float* x  = (const float*)d_in[0];
    const float* w1 = (const float*)d_in[1];
    const float* w3 = (const float*)d_in[2];
    const float* w2 = (const float*)d_in[3];
    float* out = (float*)d_out;

    void *p_xh, *p_w1h, *p_w3h, *p_w2h;
    cudaGetSymbolAddress(&p_xh,  g_xh);
    cudaGetSymbolAddress(&p_w1h, g_w1h);
    cudaGetSymbolAddress(&p_w3h, g_w3h);
    cudaGetSymbolAddress(&p_w2h, g_w2h);

    const int nx4 = (int)((size_t)B_ * E_ * C_ * D_ / 4);  // 16,777,216
    const int nw4 = (int)((size_t)E_ * D_ * F_ / 4);       //  5,767,168

    cvt_kernel<<<(nx4 + 255) / 256, 256>>>((const float4*)x,  (__half2*)p_xh,  nx4);
    cvt_kernel<<<(nw4 + 255) / 256, 256>>>((const float4*)w1, (__half2*)p_w1h, nw4);
    cvt_kernel<<<(nw4 + 255) / 256, 256>>>((const float4*)w3, (__half2*)p_w3h, nw4);
    cvt_kernel<<<(nw4 + 255) / 256, 256>>>((const float4*)w2, (__half2*)p_w2h, nw4);

    dim3 g1(F_ / BN, C_ / BM, B_ * E_);  // (44, 16, 32)
    gemm1_kernel<<<g1, 256>>>();

    dim3 g2(D_ / BN, C_ / BM, B_ * E_);  // (16, 16, 32)
    gemm2_kernel<<<g2, 256>>>(out);
}